// round 3
// baseline (speedup 1.0000x reference)
#include <cuda_runtime.h>
#include <cuda_bf16.h>

// Problem constants
#define S_TOK 8192
#define D_DIM 2048
#define E_EXP 64
#define CAP   128
#define SEC   (S_TOK * E_EXP * CAP)   // 67108864

// -------------------- device scratch (no allocation allowed) --------------------
__device__ float g_gate[S_TOK];     // gate value of chosen expert per token
__device__ int   g_expert[S_TOK];   // argmax expert per token
__device__ int   g_loc[S_TOK];      // position in expert queue (exclusive prefix)
__device__ int   g_off[S_TOK];      // flat index into [S,E,C] of the nonzero, or -1
__device__ float g_me[E_EXP];       // sum over tokens of gates[:,e]
__device__ int   g_cnt[E_EXP];      // tokens assigned to e
__device__ float g_laux;

// -------------------- host-side stream/event (created before harness checkpoint) ----
struct GExec {
    cudaStream_t s2;
    cudaEvent_t  evFork, evJoin;
    GExec() {
        cudaStreamCreateWithFlags(&s2, cudaStreamNonBlocking);
        cudaEventCreateWithFlags(&evFork, cudaEventDisableTiming);
        cudaEventCreateWithFlags(&evJoin, cudaEventDisableTiming);
    }
};
static GExec g_exec;

// -------------------- packed fp32 FMA (FFMA2) --------------------
__device__ __forceinline__ void ffma2(float2& d, const float2& a, const float2& b) {
    unsigned long long dd = *(const unsigned long long*)&d;
    unsigned long long aa = *(const unsigned long long*)&a;
    unsigned long long bb = *(const unsigned long long*)&b;
    asm("fma.rn.f32x2 %0, %1, %2, %0;" : "+l"(dd) : "l"(aa), "l"(bb));
    d = *(float2*)&dd;
}

// -------------------- init --------------------
__global__ void k_init() {
    if (threadIdx.x < E_EXP) g_me[threadIdx.x] = 0.0f;
}

// -------------------- bulk zero fill at SM store bandwidth --------------------
// 16B stores, evict-first (.cs) so the 536MB of zeros doesn't thrash L2 reuse.
__global__ __launch_bounds__(256) void k_zero(float4* __restrict__ out4, int n4,
                                              float* __restrict__ out, int nfl) {
    const float4 z = make_float4(0.f, 0.f, 0.f, 0.f);
    int i = blockIdx.x * blockDim.x + threadIdx.x;
    const int stride = gridDim.x * blockDim.x;
    for (; i < n4; i += stride) __stcs(&out4[i], z);
    // tail floats (nfl % 4)
    if (blockIdx.x == 0 && threadIdx.x < 4) {
        int f = 4 * n4 + threadIdx.x;
        if (f < nfl) out[f] = 0.0f;
    }
}

// -------------------- GEMM + softmax + argmax --------------------
// BM=64 tokens/block, BN=64 experts (all), BK=32. 256 threads = 16x16.
#define ASTRIDE 34
__global__ __launch_bounds__(256) void k_gate(const float* __restrict__ x,
                                              const float* __restrict__ wg) {
    __shared__ float sm[2 * 64 * ASTRIDE];   // 4352 floats; reused as logits later
    __shared__ float smax[64], sinv[64];
    float* sA = sm;                  // [64 tokens][34]
    float* sB = sm + 64 * ASTRIDE;   // [64 experts][34]

    const int tid = threadIdx.x;
    const int tx = tid & 15, ty = tid >> 4;
    const int m0 = blockIdx.x * 64;

    float2 acc[4][4];
#pragma unroll
    for (int i = 0; i < 4; i++)
#pragma unroll
        for (int j = 0; j < 4; j++) acc[i][j] = make_float2(0.f, 0.f);

    for (int k0 = 0; k0 < D_DIM; k0 += 32) {
        __syncthreads();
#pragma unroll
        for (int r = 0; r < 2; r++) {
            int q = tid + r * 256;
            int m = q >> 3, kq = q & 7;
            float4 vx = *(const float4*)(x + (size_t)(m0 + m) * D_DIM + k0 + kq * 4);
            float2* pa = (float2*)&sA[m * ASTRIDE + kq * 4];
            pa[0] = make_float2(vx.x, vx.y);
            pa[1] = make_float2(vx.z, vx.w);
            float4 vw = *(const float4*)(wg + (size_t)m * D_DIM + k0 + kq * 4);
            float2* pb = (float2*)&sB[m * ASTRIDE + kq * 4];
            pb[0] = make_float2(vw.x, vw.y);
            pb[1] = make_float2(vw.z, vw.w);
        }
        __syncthreads();

#pragma unroll
        for (int kk = 0; kk < 16; kk++) {
            float2 a[4], b[4];
#pragma unroll
            for (int i = 0; i < 4; i++)
                a[i] = *(const float2*)&sA[(ty + 16 * i) * ASTRIDE + 2 * kk];
#pragma unroll
            for (int j = 0; j < 4; j++)
                b[j] = *(const float2*)&sB[(tx + 16 * j) * ASTRIDE + 2 * kk];
#pragma unroll
            for (int i = 0; i < 4; i++)
#pragma unroll
                for (int j = 0; j < 4; j++) ffma2(acc[i][j], a[i], b[j]);
        }
    }
    __syncthreads();

    float* logits = sm;
#pragma unroll
    for (int i = 0; i < 4; i++)
#pragma unroll
        for (int j = 0; j < 4; j++)
            logits[(ty + 16 * i) * 65 + (tx + 16 * j)] = acc[i][j].x + acc[i][j].y;
    __syncthreads();

    if (tid < 64) {
        const float* row = &logits[tid * 65];
        float mx = row[0];
        int am = 0;
#pragma unroll 8
        for (int e = 1; e < 64; e++) {
            float v = row[e];
            if (v > mx) { mx = v; am = e; }
        }
        float sum = 0.f;
#pragma unroll 8
        for (int e = 0; e < 64; e++) sum += expf(row[e] - mx);
        float gate = 1.0f / sum;   // exp(mx-mx)/sum
        g_gate[m0 + tid] = gate;
        g_expert[m0 + tid] = am;
        smax[tid] = mx;
        sinv[tid] = gate;
    }
    __syncthreads();

    if (tid < 64) {
        float cs = 0.f;
#pragma unroll 8
        for (int t = 0; t < 64; t++)
            cs += expf(logits[t * 65 + tid] - smax[t]) * sinv[t];
        atomicAdd(&g_me[tid], cs);
    }
}

// -------------------- ordered per-expert prefix scan --------------------
__global__ __launch_bounds__(256) void k_scan() {
    const int e = blockIdx.x;
    const int tid = threadIdx.x;
    __shared__ int ws[8];
    __shared__ int stot;
    int carry = 0;
    for (int it = 0; it < S_TOK / 256; it++) {
        int s = it * 256 + tid;
        int ind = (g_expert[s] == e);
        unsigned bal = __ballot_sync(0xffffffffu, ind);
        int lane = tid & 31, w = tid >> 5;
        int pre = __popc(bal & ((1u << lane) - 1u));
        if (lane == 0) ws[w] = __popc(bal);
        __syncthreads();
        if (tid == 0) {
            int a = 0;
#pragma unroll
            for (int i = 0; i < 8; i++) { int t = ws[i]; ws[i] = a; a += t; }
            stot = a;
        }
        __syncthreads();
        if (ind) g_loc[s] = carry + ws[w] + pre;
        carry += stot;
        __syncthreads();
    }
    if (tid == 0) g_cnt[e] = carry;
}

// -------------------- offsets + l_aux --------------------
__global__ __launch_bounds__(256) void k_meta() {
    int s = blockIdx.x * 256 + threadIdx.x;
    if (s < S_TOK) {
        int e = g_expert[s], loc = g_loc[s];
        g_off[s] = (loc < CAP) ? (s * (E_EXP * CAP) + e * CAP + loc) : -1;
    }
    if (blockIdx.x == 0 && threadIdx.x < 64) {
        __shared__ float red[2];
        float v = g_me[threadIdx.x] * (float)g_cnt[threadIdx.x];
#pragma unroll
        for (int o = 16; o; o >>= 1) v += __shfl_down_sync(0xffffffffu, v, o);
        if ((threadIdx.x & 31) == 0) red[threadIdx.x >> 5] = v;
        __syncthreads();
        if (threadIdx.x == 0)
            g_laux = (red[0] + red[1]) * (64.0f / (8192.0f * 8192.0f));
    }
}

// -------------------- sparse scatter of nonzeros --------------------
// out layout: [0]=l_aux, [1..SEC]=combine (s,e,c row-major), [1+SEC..1+2*SEC]=mask
__global__ __launch_bounds__(256) void k_scatter(float* __restrict__ out) {
    int s = blockIdx.x * 256 + threadIdx.x;
    if (s == 0) out[0] = g_laux;
    if (s < S_TOK) {
        int off = g_off[s];
        if (off >= 0) {
            out[1 + (size_t)off] = g_gate[s];
            out[1 + (size_t)SEC + (size_t)off] = 1.0f;
        }
    }
}

// -------------------- launch --------------------
extern "C" void kernel_launch(void* const* d_in, const int* in_sizes, int n_in,
                              void* d_out, int out_size) {
    const float* x  = (const float*)d_in[0];
    const float* wg = (const float*)d_in[1];
    float* out = (float*)d_out;

    // Fork side stream: SM-bandwidth zero of the (almost entirely zero)
    // output, concurrent with the gate pipeline on the main stream.
    cudaEventRecord(g_exec.evFork, 0);
    cudaStreamWaitEvent(g_exec.s2, g_exec.evFork, 0);
    int n4 = out_size >> 2;
    k_zero<<<2048, 256, 0, g_exec.s2>>>((float4*)out, n4, out, out_size);

    // Gate pipeline on the main (legacy) stream.
    k_init<<<1, 64>>>();
    k_gate<<<S_TOK / 64, 256>>>(x, wg);
    k_scan<<<E_EXP, 256>>>();
    k_meta<<<S_TOK / 256, 256>>>();

    // Join, then scatter the 16385 nonzeros.
    cudaEventRecord(g_exec.evJoin, g_exec.s2);
    cudaStreamWaitEvent(0, g_exec.evJoin, 0);
    k_scatter<<<S_TOK / 256, 256>>>(out);
}

// round 4
// speedup vs baseline: 1.0496x; 1.0496x over previous
#include <cuda_runtime.h>
#include <cuda_bf16.h>

// Problem constants
#define S_TOK 8192
#define D_DIM 2048
#define E_EXP 64
#define CAP   128
#define SEC   (S_TOK * E_EXP * CAP)   // 67108864

// Output split: first A_BYTES zeroed by CE memsets (overlapped with gate
// pipeline), remaining floats zeroed by SM stores after the gate pipeline.
#define A_BYTES   335544320u          // 320 MB, 16B-multiple
#define A_FLOATS  (A_BYTES / 4u)      // 83886080
// B region: floats [A_FLOATS, 134217729) = 50331649 floats
#define B_N4      12582912            // float4 count in B region
#define LAST_F    134217728           // final tail float index

// -------------------- device scratch --------------------
__device__ float g_gate[S_TOK];
__device__ int   g_expert[S_TOK];
__device__ int   g_loc[S_TOK];
__device__ int   g_off[S_TOK];
__device__ float g_me_part[(S_TOK / 64) * E_EXP];  // per-block column sums
__device__ int   g_cnt[E_EXP];
__device__ float g_laux;

// -------------------- host-side streams/events --------------------
struct GExec {
    cudaStream_t s2, s3;
    cudaEvent_t  evFork, evJoin2, evJoin3;
    GExec() {
        cudaStreamCreateWithFlags(&s2, cudaStreamNonBlocking);
        cudaStreamCreateWithFlags(&s3, cudaStreamNonBlocking);
        cudaEventCreateWithFlags(&evFork,  cudaEventDisableTiming);
        cudaEventCreateWithFlags(&evJoin2, cudaEventDisableTiming);
        cudaEventCreateWithFlags(&evJoin3, cudaEventDisableTiming);
    }
};
static GExec g_exec;

// -------------------- packed fp32 FMA (FFMA2) --------------------
__device__ __forceinline__ void ffma2(float2& d, const float2& a, const float2& b) {
    unsigned long long dd = *(const unsigned long long*)&d;
    unsigned long long aa = *(const unsigned long long*)&a;
    unsigned long long bb = *(const unsigned long long*)&b;
    asm("fma.rn.f32x2 %0, %1, %2, %0;" : "+l"(dd) : "l"(aa), "l"(bb));
    d = *(float2*)&dd;
}

// -------------------- SM zero fill of region B (runs AFTER gate pipeline) ---
__global__ __launch_bounds__(256) void k_zero(float4* __restrict__ b4,
                                              float* __restrict__ out) {
    int i = blockIdx.x * 256 + threadIdx.x;
    if (i < B_N4) b4[i] = make_float4(0.f, 0.f, 0.f, 0.f);
    if (i == 0) out[LAST_F] = 0.0f;
}

// -------------------- GEMM + softmax + argmax --------------------
// BM=64 tokens/block, BN=64 experts, BK=32. 256 threads = 16x16.
// ASTRIDE=36 floats (9 float4): 16B-aligned rows -> LDS.128 smem reads,
// conflict-optimal (a: 2-way broadcast, b: 2 phases = crossbar floor).
#define ASTRIDE 36
__global__ __launch_bounds__(256) void k_gate(const float* __restrict__ x,
                                              const float* __restrict__ wg) {
    __shared__ float sm[2 * 64 * ASTRIDE];   // 4608 floats; reused as logits
    __shared__ float smax[64], sinv[64];
    float* sA = sm;
    float* sB = sm + 64 * ASTRIDE;

    const int tid = threadIdx.x;
    const int tx = tid & 15, ty = tid >> 4;
    const int m0 = blockIdx.x * 64;

    float2 acc[4][4];
#pragma unroll
    for (int i = 0; i < 4; i++)
#pragma unroll
        for (int j = 0; j < 4; j++) acc[i][j] = make_float2(0.f, 0.f);

    for (int k0 = 0; k0 < D_DIM; k0 += 32) {
        __syncthreads();
#pragma unroll
        for (int r = 0; r < 2; r++) {
            int q = tid + r * 256;
            int m = q >> 3, kq = q & 7;
            float4 vx = *(const float4*)(x + (size_t)(m0 + m) * D_DIM + k0 + kq * 4);
            *(float4*)&sA[m * ASTRIDE + kq * 4] = vx;
            float4 vw = *(const float4*)(wg + (size_t)m * D_DIM + k0 + kq * 4);
            *(float4*)&sB[m * ASTRIDE + kq * 4] = vw;
        }
        __syncthreads();

#pragma unroll
        for (int kk8 = 0; kk8 < 8; kk8++) {
            float4 a4[4], b4[4];
#pragma unroll
            for (int i = 0; i < 4; i++)
                a4[i] = *(const float4*)&sA[(ty + 16 * i) * ASTRIDE + kk8 * 4];
#pragma unroll
            for (int j = 0; j < 4; j++)
                b4[j] = *(const float4*)&sB[(tx + 16 * j) * ASTRIDE + kk8 * 4];
#pragma unroll
            for (int i = 0; i < 4; i++) {
                const float2* ap = (const float2*)&a4[i];
#pragma unroll
                for (int j = 0; j < 4; j++) {
                    const float2* bp = (const float2*)&b4[j];
                    ffma2(acc[i][j], ap[0], bp[0]);
                    ffma2(acc[i][j], ap[1], bp[1]);
                }
            }
        }
    }
    __syncthreads();

    float* logits = sm;   // [64][65]
#pragma unroll
    for (int i = 0; i < 4; i++)
#pragma unroll
        for (int j = 0; j < 4; j++)
            logits[(ty + 16 * i) * 65 + (tx + 16 * j)] = acc[i][j].x + acc[i][j].y;
    __syncthreads();

    if (tid < 64) {
        const float* row = &logits[tid * 65];
        float mx = row[0];
        int am = 0;
#pragma unroll 8
        for (int e = 1; e < 64; e++) {
            float v = row[e];
            if (v > mx) { mx = v; am = e; }
        }
        float sum = 0.f;
#pragma unroll 8
        for (int e = 0; e < 64; e++) sum += expf(row[e] - mx);
        float gate = 1.0f / sum;
        g_gate[m0 + tid] = gate;
        g_expert[m0 + tid] = am;
        smax[tid] = mx;
        sinv[tid] = gate;
    }
    __syncthreads();

    if (tid < 64) {
        float cs = 0.f;
#pragma unroll 8
        for (int t = 0; t < 64; t++)
            cs += expf(logits[t * 65 + tid] - smax[t]) * sinv[t];
        g_me_part[blockIdx.x * 64 + tid] = cs;   // no atomics, no init kernel
    }
}

// -------------------- ordered per-expert prefix scan --------------------
__global__ __launch_bounds__(256) void k_scan() {
    const int e = blockIdx.x;
    const int tid = threadIdx.x;
    __shared__ int ws[8];
    __shared__ int stot;
    int carry = 0;
    for (int it = 0; it < S_TOK / 256; it++) {
        int s = it * 256 + tid;
        int ind = (g_expert[s] == e);
        unsigned bal = __ballot_sync(0xffffffffu, ind);
        int lane = tid & 31, w = tid >> 5;
        int pre = __popc(bal & ((1u << lane) - 1u));
        if (lane == 0) ws[w] = __popc(bal);
        __syncthreads();
        if (tid == 0) {
            int a = 0;
#pragma unroll
            for (int i = 0; i < 8; i++) { int t = ws[i]; ws[i] = a; a += t; }
            stot = a;
        }
        __syncthreads();
        if (ind) g_loc[s] = carry + ws[w] + pre;
        carry += stot;
        __syncthreads();
    }
    if (tid == 0) g_cnt[e] = carry;
}

// -------------------- offsets + l_aux --------------------
__global__ __launch_bounds__(256) void k_meta() {
    int s = blockIdx.x * 256 + threadIdx.x;
    if (s < S_TOK) {
        int e = g_expert[s], loc = g_loc[s];
        g_off[s] = (loc < CAP) ? (s * (E_EXP * CAP) + e * CAP + loc) : -1;
    }
    if (blockIdx.x == 0 && threadIdx.x < 64) {
        __shared__ float red[2];
        float me = 0.f;
#pragma unroll 8
        for (int b = 0; b < S_TOK / 64; b++)
            me += g_me_part[b * 64 + threadIdx.x];
        float v = me * (float)g_cnt[threadIdx.x];
#pragma unroll
        for (int o = 16; o; o >>= 1) v += __shfl_down_sync(0xffffffffu, v, o);
        if ((threadIdx.x & 31) == 0) red[threadIdx.x >> 5] = v;
        __syncthreads();
        if (threadIdx.x == 0)
            g_laux = (red[0] + red[1]) * (64.0f / (8192.0f * 8192.0f));
    }
}

// -------------------- sparse scatter of nonzeros --------------------
__global__ __launch_bounds__(256) void k_scatter(float* __restrict__ out) {
    int s = blockIdx.x * 256 + threadIdx.x;
    if (s == 0) out[0] = g_laux;
    if (s < S_TOK) {
        int off = g_off[s];
        if (off >= 0) {
            out[1 + (size_t)off] = g_gate[s];
            out[1 + (size_t)SEC + (size_t)off] = 1.0f;
        }
    }
}

// -------------------- launch --------------------
extern "C" void kernel_launch(void* const* d_in, const int* in_sizes, int n_in,
                              void* d_out, int out_size) {
    const float* x  = (const float*)d_in[0];
    const float* wg = (const float*)d_in[1];
    float* out = (float*)d_out;

    // Fork: two CE memsets zero the first 320MB concurrently with the gate
    // pipeline (copy engines -> no SM contention).
    cudaEventRecord(g_exec.evFork, 0);
    cudaStreamWaitEvent(g_exec.s2, g_exec.evFork, 0);
    cudaStreamWaitEvent(g_exec.s3, g_exec.evFork, 0);
    cudaMemsetAsync(out, 0, A_BYTES / 2, g_exec.s2);
    cudaMemsetAsync((char*)out + A_BYTES / 2, 0, A_BYTES / 2, g_exec.s3);
    cudaEventRecord(g_exec.evJoin2, g_exec.s2);
    cudaEventRecord(g_exec.evJoin3, g_exec.s3);

    // Gate pipeline on the main stream (SMs are exclusively ours here).
    k_gate<<<S_TOK / 64, 256>>>(x, wg);
    k_scan<<<E_EXP, 256>>>();
    k_meta<<<S_TOK / 256, 256>>>();

    // SM zero of the last 192MB — starts only after the gate pipeline, so no
    // SM-level interference.
    k_zero<<<(B_N4 + 255) / 256, 256>>>((float4*)(out + A_FLOATS), out);

    // Join CE branches, then scatter the 16385 nonzeros.
    cudaStreamWaitEvent(0, g_exec.evJoin2, 0);
    cudaStreamWaitEvent(0, g_exec.evJoin3, 0);
    k_scatter<<<S_TOK / 256, 256>>>(out);
}